// round 12
// baseline (speedup 1.0000x reference)
#include <cuda_runtime.h>
#include <cuda_fp16.h>
#include <cstdint>
#include <math.h>

#define kVocab 50000
#define kEmbed 300
#define kEmbP  320
#define kUnits 512
#define kT 128
#define kB 512
#define kG 2048

// ---------------- global scratch ----------------
__device__ float g_zpre[(size_t)kB * kT * kG];
__device__ float g_c[(size_t)kB * kUnits];
// U^T gate-interleaved, fp16, PRE-SWIZZLED chunk-block layout:
//   [nt(16)][kc(8)][block 16KB = 128 rows x 64k], elem idx per block:
//   r*64 + ((q ^ (r&7))<<3) + ln   with q=(k>>3)&7, ln=k&7
__device__ __align__(128) __half g_u_blk[kG * kUnits];
// h fp16, double buffered, PRE-SWIZZLED blocks: [mt(8)][kc(8)][block 8KB = 64 rows x 64k]
__device__ __align__(128) __half g_hb_blk[2][kB * kUnits];
__device__ __align__(128) __half g_emb_hi[(size_t)kVocab * kEmbP];
__device__ __align__(128) __half g_emb_lo[(size_t)kVocab * kEmbP];
__device__ __align__(128) __half g_wt[kG * kEmbP];

// ---------------- helpers ----------------
__device__ __forceinline__ uint32_t smem_u32(const void* p) {
    uint32_t a;
    asm("{ .reg .u64 t; cvta.to.shared.u64 t, %1; cvt.u32.u64 %0, t; }" : "=r"(a) : "l"(p));
    return a;
}
#define CP_ASYNC16(dst, src) \
    asm volatile("cp.async.cg.shared.global [%0], [%1], 16;" :: "r"(dst), "l"(src) : "memory")
#define CP_COMMIT() asm volatile("cp.async.commit_group;" ::: "memory")
#define CP_WAIT0()  asm volatile("cp.async.wait_group 0;" ::: "memory")

#define MBAR_INIT(a, c) \
    asm volatile("mbarrier.init.shared.b64 [%0], %1;" :: "r"(a), "r"(c) : "memory")
#define MBAR_EXPECT_TX(a, bytes) \
    asm volatile("mbarrier.arrive.expect_tx.shared.b64 _, [%0], %1;" :: "r"(a), "r"(bytes) : "memory")
#define TMA_BULK(dst, src, sz, mbar) \
    asm volatile("cp.async.bulk.shared::cta.global.mbarrier::complete_tx::bytes [%0], [%1], %2, [%3];" \
        :: "r"(dst), "l"(src), "r"(sz), "r"(mbar) : "memory")
#define MBAR_WAIT(a, par) do { \
    uint32_t _m = (a), _p = (par), _d; \
    asm volatile("{ .reg .pred p; mbarrier.try_wait.parity.acquire.cta.shared::cta.b64 p, [%1], %2; selp.b32 %0,1,0,p; }" \
        : "=r"(_d) : "r"(_m), "r"(_p) : "memory"); \
    if (!_d) { \
        asm volatile("{ .reg .pred P1; WL%=: mbarrier.try_wait.parity.acquire.cta.shared::cta.b64 P1, [%0], %1, 0x989680; @P1 bra.uni WD%=; bra.uni WL%=; WD%=: }" \
            :: "r"(_m), "r"(_p) : "memory"); \
    } } while (0)

#define LDMATRIX_X4(r0, r1, r2, r3, addr) \
    asm volatile("ldmatrix.sync.aligned.m8n8.x4.shared.b16 {%0,%1,%2,%3}, [%4];" \
        : "=r"(r0), "=r"(r1), "=r"(r2), "=r"(r3) : "r"(addr))

#define MMA_F16(c0, c1, c2, c3, a0, a1, a2, a3, b0, b1) \
    asm volatile("mma.sync.aligned.m16n8k16.row.col.f32.f16.f16.f32 " \
        "{%0,%1,%2,%3}, {%4,%5,%6,%7}, {%8,%9}, {%0,%1,%2,%3};" \
        : "+f"(c0), "+f"(c1), "+f"(c2), "+f"(c3) \
        : "r"(a0), "r"(a1), "r"(a2), "r"(a3), "r"(b0), "r"(b1))

__device__ __forceinline__ float fast_ex2(float x) { float y; asm("ex2.approx.ftz.f32 %0, %1;" : "=f"(y) : "f"(x)); return y; }
__device__ __forceinline__ float fast_sig(float x) { return __fdividef(1.f, 1.f + fast_ex2(-1.4426950408889634f * x)); }
__device__ __forceinline__ float fast_tanh(float x) {
    float ax = fabsf(x);
    float e = fast_ex2(-2.8853900817779268f * ax);
    float t = __fdividef(1.f - e, 1.f + e);
    return copysignf(t, x);
}
__device__ __forceinline__ void split_f16(float v, __half& hi, __half& lo) {
    hi = __float2half_rn(v);
    lo = __float2half_rn(v - __half2float(hi));
}

// ---------------- prep ----------------
__global__ __launch_bounds__(128) void prep_kernel(const float* __restrict__ U,
                                                   const float* __restrict__ h0,
                                                   const float* __restrict__ W,
                                                   const float* __restrict__ emb) {
    int blk = blockIdx.x;
    if (blk < kG) {                       // U^T gate-interleaved n'=u*4+g -> swizzled blocks
        int np = blk;
        int n = (np & 3) * kUnits + (np >> 2);
        int nt = np >> 7, rl = np & 127;
        for (int k = threadIdx.x; k < kUnits; k += 128) {
            int kc = k >> 6, q = (k >> 3) & 7, ln = k & 7;
            size_t idx = (size_t)(nt * 8 + kc) * 8192 + rl * 64 + ((q ^ (rl & 7)) << 3) + ln;
            g_u_blk[idx] = __float2half_rn(__ldg(U + (size_t)k * kG + n));
        }
    } else if (blk < kG + 8) {            // h0 -> fp16 swizzled blocks, buffer 1
        int mt = blk - kG;
        int r0 = mt * 64;
        for (int i = threadIdx.x; i < 64 * kUnits; i += 128) {
            int rb = i >> 9, k = i & 511;
            int kc = k >> 6, q = (k >> 3) & 7, ln = k & 7;
            size_t idx = (size_t)(mt * 8 + kc) * 4096 + rb * 64 + ((q ^ (rb & 7)) << 3) + ln;
            g_hb_blk[1][idx] = __float2half_rn(__ldg(h0 + (size_t)(r0 + rb) * kUnits + k));
        }
    } else if (blk < kG + 8 + kG) {       // W^T row n, padded K, fp16 (linear; precompute uses cp.async)
        int n = blk - kG - 8;
        for (int k = threadIdx.x; k < kEmbP; k += 128) {
            float v = (k < kEmbed) ? __ldg(W + (size_t)k * kG + n) : 0.f;
            g_wt[n * kEmbP + k] = __float2half_rn(v);
        }
    } else {                              // emb rows, padded, fp16 hi/lo
        int r0 = (blk - kG - 8 - kG) * 8;
        for (int rr = 0; rr < 8; rr++) {
            int row = r0 + rr;
            if (row >= kVocab) break;
            for (int k = threadIdx.x; k < kEmbP; k += 128) {
                float v = (k < kEmbed) ? __ldg(emb + (size_t)row * kEmbed + k) : 0.f;
                __half hi, lo;
                split_f16(v, hi, lo);
                g_emb_hi[(size_t)row * kEmbP + k] = hi;
                g_emb_lo[(size_t)row * kEmbP + k] = lo;
            }
        }
    }
}

// ---------------- precompute Zpre via mma.sync (R10/R11, proven) ----------------
#define PC_STG 49152
#define PC_DYN 98304

extern "C" __global__ void __launch_bounds__(256, 1) precompute_mma_kernel(
    const int* __restrict__ seq, const float* __restrict__ bias)
{
    extern __shared__ __align__(1024) char smp[];
    const uint32_t smb = smem_u32(smp);
    __shared__ int toks[128];

    const int tid = threadIdx.x;
    const int wid = tid >> 5, lane = tid & 31;
    const int nt = blockIdx.x, b = blockIdx.y;
    const int n0 = nt * 128;

    if (tid < 128) toks[tid] = seq[(size_t)b * kT + tid];
    __syncthreads();

    const int wm = (wid & 1) * 64;
    const int wn = (wid >> 1) * 32;

    float acc[4][4][4];
#pragma unroll
    for (int i = 0; i < 4; i++)
#pragma unroll
        for (int j = 0; j < 4; j++)
#pragma unroll
            for (int q = 0; q < 4; q++) acc[i][j][q] = 0.f;

    auto issue_chunk = [&](int kc, int stg) {
#pragma unroll
        for (int i = 0; i < 12; i++) {
            int idx = i * 256 + tid;
            uint32_t dst;
            const __half* src;
            if (idx < 2048) {
                int mat = idx >> 10, r = (idx >> 3) & 127, q = idx & 7;
                src = (mat ? g_emb_lo : g_emb_hi) + (size_t)toks[r] * kEmbP + kc * 64 + q * 8;
                uint32_t off = (uint32_t)(r * 128 + ((q ^ (r & 7)) * 16));
                dst = smb + stg * PC_STG + mat * 16384 + off;
            } else {
                int idxB = idx - 2048;
                int r = (idxB >> 3) & 127, q = idxB & 7;
                src = g_wt + (size_t)(n0 + r) * kEmbP + kc * 64 + q * 8;
                uint32_t off = (uint32_t)(r * 128 + ((q ^ (r & 7)) * 16));
                dst = smb + stg * PC_STG + 32768 + off;
            }
            CP_ASYNC16(dst, src);
        }
        CP_COMMIT();
    };

    issue_chunk(0, 0);

    const int la7 = lane & 7;
    const int arow_off = (lane >> 3) & 1;
    const int akseg   = (lane >> 4) & 1;
    const int brow_off = (lane >> 4) & 1;
    const int bkseg   = (lane >> 3) & 1;

    for (int kc = 0; kc < 5; kc++) {
        CP_WAIT0();
        __syncthreads();
        if (kc < 4) issue_chunk(kc + 1, (kc + 1) & 1);

        const uint32_t base = smb + (kc & 1) * PC_STG;
#pragma unroll
        for (int ks = 0; ks < 4; ks++) {
            uint32_t ahi[4][4], alo[4][4], bb[2][4];
#pragma unroll
            for (int mf = 0; mf < 4; mf++) {
                int row = wm + mf * 16 + la7 + arow_off * 8;
                uint32_t off = (uint32_t)(row * 128 + ks * 32 + akseg * 16);
                off ^= (uint32_t)((row & 7) * 16);
                LDMATRIX_X4(ahi[mf][0], ahi[mf][1], ahi[mf][2], ahi[mf][3], base + off);
                LDMATRIX_X4(alo[mf][0], alo[mf][1], alo[mf][2], alo[mf][3], base + 16384 + off);
            }
#pragma unroll
            for (int p = 0; p < 2; p++) {
                int row = wn + p * 16 + la7 + brow_off * 8;
                uint32_t off = (uint32_t)(row * 128 + ks * 32 + bkseg * 16);
                off ^= (uint32_t)((row & 7) * 16);
                LDMATRIX_X4(bb[p][0], bb[p][1], bb[p][2], bb[p][3], base + 32768 + off);
            }
#pragma unroll
            for (int mf = 0; mf < 4; mf++)
#pragma unroll
                for (int nf = 0; nf < 4; nf++) {
                    const int p = nf >> 1, s = (nf & 1) * 2;
                    float* c = acc[mf][nf];
                    MMA_F16(c[0], c[1], c[2], c[3],
                            ahi[mf][0], ahi[mf][1], ahi[mf][2], ahi[mf][3],
                            bb[p][s], bb[p][s + 1]);
                    MMA_F16(c[0], c[1], c[2], c[3],
                            alo[mf][0], alo[mf][1], alo[mf][2], alo[mf][3],
                            bb[p][s], bb[p][s + 1]);
                }
        }
    }

    __syncthreads();
    float* zs = (float*)smp;
    {
        const int cr = lane >> 2, cc = (lane & 3) * 2;
#pragma unroll
        for (int mf = 0; mf < 4; mf++)
#pragma unroll
            for (int nf = 0; nf < 4; nf++) {
                int row = wm + mf * 16 + cr;
                int col = wn + nf * 8 + cc;
                *(float2*)&zs[row * 128 + col]       = make_float2(acc[mf][nf][0], acc[mf][nf][1]);
                *(float2*)&zs[(row + 8) * 128 + col] = make_float2(acc[mf][nf][2], acc[mf][nf][3]);
            }
    }
    __syncthreads();

    const int cseg = tid & 31;
    float4 bv = __ldg((const float4*)(bias + n0 + cseg * 4));
#pragma unroll
    for (int i = 0; i < 16; i++) {
        int r = i * 8 + (tid >> 5);
        float4 v = *(const float4*)&zs[r * 128 + cseg * 4];
        v.x += bv.x; v.y += bv.y; v.z += bv.z; v.w += bv.w;
        *(float4*)(g_zpre + ((size_t)b * kT + r) * kG + n0 + cseg * 4) = v;
    }
}

// ---------------- mma.sync LSTM step with TMA bulk staging ----------------
// grid (16 nt, 8 mt) = 128 CTAs, 256 thr (8 warps 2x4), warp tile 32x32.
// CTA tile M=64 x N=128, K=512 in 8 chunks of 64.
// stage: A 8KB + B 16KB = 24KB; 3 stages = 72KB. One TMA pair per chunk.
#define ST_STG 24576
#define ST_DYN 73728
#define CHUNK_BYTES 24576u

extern "C" __global__ void __launch_bounds__(256, 1) step_mma_kernel(
    int t,
    const int* __restrict__ seq,
    const float* __restrict__ hprev_f32, int hstride,
    const float* __restrict__ c0,
    float* __restrict__ out)
{
    extern __shared__ __align__(1024) char smp[];
    __shared__ __align__(8) uint64_t mbars[3];
    const uint32_t smb = smem_u32(smp);
    const uint32_t mb0 = smem_u32(mbars);

    const int tid = threadIdx.x;
    const int wid = tid >> 5, lane = tid & 31;
    const int nt = blockIdx.x, mt = blockIdx.y;
    const int b0 = mt * 64;
    const int u0g = nt * 32;

    // ---- epilogue operand prefetch (overlaps GEMM) ----
    const int ul = tid & 31;
    float zpf[8][4], cpre[8];
    int seqv[8];
    {
        const float* cin = (t == 0) ? c0 : g_c;
#pragma unroll
        for (int it = 0; it < 8; it++) {
            int r = it * 8 + (tid >> 5);
            int bb = b0 + r;
            const float* zp = g_zpre + ((size_t)bb * kT + t) * kG;
#pragma unroll
            for (int g = 0; g < 4; g++)
                zpf[it][g] = __ldg(zp + g * kUnits + u0g + ul);
            cpre[it] = __ldg(cin + (size_t)bb * kUnits + u0g + ul);
            seqv[it] = __ldg(seq + (size_t)bb * kT + t);
        }
    }

    const __half* srcA = g_hb_blk[(t + 1) & 1] + (size_t)mt * 8 * 4096;  // 8KB blocks
    const __half* srcB = g_u_blk + (size_t)nt * 8 * 8192;                // 16KB blocks

    if (tid == 0) {
        MBAR_INIT(mb0, 1);
        MBAR_INIT(mb0 + 8, 1);
        MBAR_INIT(mb0 + 16, 1);
    }
    __syncthreads();

    auto issue_chunk = [&](int kc, int stg) {
        uint32_t mb = mb0 + stg * 8;
        MBAR_EXPECT_TX(mb, CHUNK_BYTES);
        TMA_BULK(smb + stg * ST_STG,        srcA + (size_t)kc * 4096, 8192u,  mb);
        TMA_BULK(smb + stg * ST_STG + 8192, srcB + (size_t)kc * 8192, 16384u, mb);
    };
    if (tid == 0) { issue_chunk(0, 0); issue_chunk(1, 1); }

    const int wm = (wid & 1) * 32;
    const int wn = (wid >> 1) * 32;

    float acc[2][4][4];
#pragma unroll
    for (int i = 0; i < 2; i++)
#pragma unroll
        for (int j = 0; j < 4; j++)
#pragma unroll
            for (int q = 0; q < 4; q++) acc[i][j][q] = 0.f;

    const int la7 = lane & 7;
    const int arow_off = (lane >> 3) & 1;
    const int akseg   = (lane >> 4) & 1;
    const int brow_off = (lane >> 4) & 1;
    const int bkseg   = (lane >> 3) & 1;

    for (int kc = 0; kc < 8; kc++) {
        const int stg = kc % 3;
        MBAR_WAIT(mb0 + stg * 8, (kc / 3) & 1);
        __syncthreads();
        if (kc < 6 && tid == 0) issue_chunk(kc + 2, (kc + 2) % 3);

        const uint32_t base = smb + stg * ST_STG;
#pragma unroll
        for (int ks = 0; ks < 4; ks++) {
            uint32_t aa[2][4], bb[2][4];
#pragma unroll
            for (int mf = 0; mf < 2; mf++) {
                int row = wm + mf * 16 + la7 + arow_off * 8;
                uint32_t off = (uint32_t)(row * 128 + ks * 32 + akseg * 16);
                off ^= (uint32_t)((row & 7) * 16);
                LDMATRIX_X4(aa[mf][0], aa[mf][1], aa[mf][2], aa[mf][3], base + off);
            }
#pragma unroll
            for (int p = 0; p < 2; p++) {
                int row = wn + p * 16 + la7 + brow_off * 8;
                uint32_t off = (uint32_t)(row * 128 + ks * 32 + bkseg * 16);
                off ^= (uint32_t)((row & 7) * 16);
                LDMATRIX_X4(bb[p][0], bb[p][1], bb[p][2], bb[p][3], base + 8192 + off);
            }
#pragma unroll
            for (int mf = 0; mf < 2; mf++)
#pragma unroll
                for (int nf = 0; nf < 4; nf++) {
                    const int p = nf >> 1, s = (nf & 1) * 2;
                    float* c = acc[mf][nf];
                    MMA_F16(c[0], c[1], c[2], c[3],
                            aa[mf][0], aa[mf][1], aa[mf][2], aa[mf][3],
                            bb[p][s], bb[p][s + 1]);
                }
        }
    }

    // ---- stage z to smem: 64x128 f32 = 32KB ----
    __syncthreads();
    float* zs = (float*)smp;
    {
        const int cr = lane >> 2, cc = (lane & 3) * 2;
#pragma unroll
        for (int mf = 0; mf < 2; mf++)
#pragma unroll
            for (int nf = 0; nf < 4; nf++) {
                int row = wm + mf * 16 + cr;
                int col = wn + nf * 8 + cc;
                *(float2*)&zs[row * 128 + col]       = make_float2(acc[mf][nf][0], acc[mf][nf][1]);
                *(float2*)&zs[(row + 8) * 128 + col] = make_float2(acc[mf][nf][2], acc[mf][nf][3]);
            }
    }
    __syncthreads();

    // ---- fused LSTM epilogue (+ finalize at t = T-1); h written pre-swizzled ----
    __half* dsth = g_hb_blk[t & 1];
    const bool lastt = (t == kT - 1);
    float* hfin = out + (size_t)kB * kT * kUnits;
    float* cfin = hfin + (size_t)kB * kUnits;
    const int kcw = nt >> 1;                       // h-block chunk this CTA's units fall in
    const int qbase = (nt & 1) * 4 + (ul >> 3);    // q of this unit
    const int lnw = ul & 7;
#pragma unroll
    for (int it = 0; it < 8; it++) {
        int rb = it * 8 + (tid >> 5);
        int b = b0 + rb;
        int u = u0g + ul;
        float4 z4 = *(const float4*)&zs[rb * 128 + ul * 4];
        float zi = z4.x + zpf[it][0];
        float zf = z4.y + zpf[it][1];
        float zg = z4.z + zpf[it][2];
        float zo = z4.w + zpf[it][3];
        float ig = fast_sig(zi);
        float fg = fast_sig(zf);
        float og = fast_sig(zo);
        float cold = cpre[it];
        float cnew = fmaf(fg, cold, ig * fast_tanh(zg));
        float hnew = og * fast_tanh(cnew);
        if (seqv[it] == 0) {
            cnew = cold;
            hnew = __ldg(hprev_f32 + (size_t)b * hstride + u);
        }
        g_c[(size_t)b * kUnits + u] = cnew;
        out[(size_t)b * (kT * kUnits) + (size_t)t * kUnits + u] = hnew;
        size_t hidx = (size_t)(mt * 8 + kcw) * 4096 + rb * 64 + ((qbase ^ (rb & 7)) << 3) + lnw;
        dsth[hidx] = __float2half_rn(hnew);
        if (lastt) {
            hfin[(size_t)b * kUnits + u] = hnew;
            cfin[(size_t)b * kUnits + u] = cnew;
        }
    }
}

// ---------------- host ----------------
extern "C" void kernel_launch(void* const* d_in, const int* in_sizes, int n_in,
                              void* d_out, int out_size)
{
    const int*   seq  = (const int*)d_in[0];
    const float* h0   = (const float*)d_in[1];
    const float* c0   = (const float*)d_in[2];
    const float* emb  = (const float*)d_in[3];
    const float* W    = (const float*)d_in[4];
    const float* Umat = (const float*)d_in[5];
    const float* bias = (const float*)d_in[6];
    float* out = (float*)d_out;

    static int configured = 0;
    if (!configured) {
        cudaFuncSetAttribute(precompute_mma_kernel, cudaFuncAttributeMaxDynamicSharedMemorySize, PC_DYN);
        cudaFuncSetAttribute(step_mma_kernel, cudaFuncAttributeMaxDynamicSharedMemorySize, ST_DYN);
        configured = 1;
    }

    const int embBlocks = (kVocab + 7) / 8;
    prep_kernel<<<kG + 8 + kG + embBlocks, 128>>>(Umat, h0, W, emb);

    precompute_mma_kernel<<<dim3(16, kB), 256, PC_DYN>>>(seq, bias);

    for (int t = 0; t < kT; t++) {
        const float* hprev = t ? (out + (size_t)(t - 1) * kUnits) : h0;
        int hstride = t ? (kT * kUnits) : kUnits;
        step_mma_kernel<<<dim3(16, 8), 256, ST_DYN>>>(t, seq, hprev, hstride, c0, out);
    }
}